// round 15
// baseline (speedup 1.0000x reference)
#include <cuda_runtime.h>
#include <cuda_fp16.h>
#include <math.h>

#define N_USERS 100000
#define N_NODES 150000
#define NNZ     4800000
#define EMB     64
#define N_LAYERS 3
#define BATCH   4096
#define REG_C   1e-5f
#define NE      (N_NODES * EMB)
#define HIST_SZ 150016
#define NBLK    586                      // scan blocks: 586*256 = 150016
#define HIST_GRID (NNZ / 256)            // 18750
#define EGO_GRID ((NE / 4) / 256)        // 9375
#define LGRID   ((N_NODES + 63) / 64)    // 2344

typedef unsigned long long u64;

// ---------------- scratch (alloc-free rule: __device__ globals) ------------
__device__ __half g_Xh[(N_LAYERS + 1) * NE]; // 76.8 MB fp16 planes 0..3
__device__ __half g_sideLh[NE];              // 19.2 MB fp16 spmm output
__device__ int    g_hist[HIST_SZ];           // zero at load; self-zeroed each pass
__device__ int    g_row_start[HIST_SZ];
__device__ int    g_blocksum[NBLK];
__device__ unsigned char g_rank[NNZ];        // per-edge rank within its row
__device__ uint2  g_edges[NNZ];              // (col, val as dup half2)
__device__ volatile unsigned g_bar_gen;
__device__ unsigned g_bar_ctr;

// ---------------- helpers ----------------------------------------------------
__device__ __forceinline__ __half2 as_h2(unsigned u) {
    __half2 h; *(unsigned*)&h = u; return h;
}
__device__ __forceinline__ unsigned smem_u32(const void* p) {
    return (unsigned)__cvta_generic_to_shared(p);
}
__device__ __forceinline__ void ldsm_x4(unsigned& r0, unsigned& r1,
                                        unsigned& r2, unsigned& r3,
                                        unsigned addr) {
    asm volatile("ldmatrix.sync.aligned.m8n8.x4.shared.b16 {%0,%1,%2,%3}, [%4];"
                 : "=r"(r0), "=r"(r1), "=r"(r2), "=r"(r3) : "r"(addr));
}
__device__ __forceinline__ void ldsm_x4t(unsigned& r0, unsigned& r1,
                                         unsigned& r2, unsigned& r3,
                                         unsigned addr) {
    asm volatile("ldmatrix.sync.aligned.m8n8.x4.trans.shared.b16 {%0,%1,%2,%3}, [%4];"
                 : "=r"(r0), "=r"(r1), "=r"(r2), "=r"(r3) : "r"(addr));
}
__device__ __forceinline__ void mma16816(float* c,
                                         unsigned a0, unsigned a1,
                                         unsigned a2, unsigned a3,
                                         unsigned b0, unsigned b1) {
    asm volatile(
        "mma.sync.aligned.m16n8k16.row.col.f32.f16.f16.f32 "
        "{%0,%1,%2,%3}, {%4,%5,%6,%7}, {%8,%9}, {%0,%1,%2,%3};"
        : "+f"(c[0]), "+f"(c[1]), "+f"(c[2]), "+f"(c[3])
        : "r"(a0), "r"(a1), "r"(a2), "r"(a3), "r"(b0), "r"(b1));
}

// ---------------- fused: out=0 + rank-recording hist + ego copy -------------
__global__ void hist_ego_kernel(const int* __restrict__ rows,
                                const float* __restrict__ ue,
                                const float* __restrict__ ie,
                                float* out) {
    int b = blockIdx.x;
    if (b == 0 && threadIdx.x == 0) *out = 0.f;
    if (b < HIST_GRID) {
        int e = b * 256 + threadIdx.x;
        int old = atomicAdd(&g_hist[rows[e]], 1);
        g_rank[e] = (unsigned char)old;          // rank within row (max deg ~57)
    } else {
        int idx = (b - HIST_GRID) * 256 + threadIdx.x;   // float4 index
        const int UF = (N_USERS * EMB) / 4;
        float4 v = (idx < UF) ? ((const float4*)ue)[idx]
                              : ((const float4*)ie)[idx - UF];
        __half2 h0 = __floats2half2_rn(v.x, v.y);
        __half2 h1 = __floats2half2_rn(v.z, v.w);
        ((uint2*)g_Xh)[idx] = make_uint2(*(unsigned*)&h0, *(unsigned*)&h1);
    }
}

// ---------------- single-kernel 3-stage scan (in-kernel grid barrier) -------
__global__ void __launch_bounds__(256) scan123_kernel() {
    __shared__ int s[256];
    __shared__ int red[256];
    int t = threadIdx.x;
    int b = blockIdx.x;
    int i = b * 256 + t;

    int v = g_hist[i];
    g_hist[i] = 0;
    s[t] = v; __syncthreads();
#pragma unroll
    for (int off = 1; off < 256; off <<= 1) {
        int add = (t >= off) ? s[t - off] : 0;
        __syncthreads();
        s[t] += add;
        __syncthreads();
    }
    if (t == 255) g_blocksum[b] = s[255];

    __threadfence();
    __syncthreads();
    if (t == 0) {
        unsigned gen = g_bar_gen;
        __threadfence();
        unsigned old = atomicAdd(&g_bar_ctr, 1u);
        if (old == NBLK - 1) {
            g_bar_ctr = 0;
            __threadfence();
            g_bar_gen = gen + 1;
        } else {
            while (g_bar_gen == gen) { }
        }
    }
    __syncthreads();
    __threadfence();

    int acc = 0;
    for (int k = t; k < b; k += 256) acc += g_blocksum[k];
    red[t] = acc; __syncthreads();
#pragma unroll
    for (int off = 128; off; off >>= 1) {
        if (t < off) red[t] += red[t + off];
        __syncthreads();
    }
    g_row_start[i] = (s[t] - v) + red[0];
}

// ---------------- scatter (atomic-free): pos = row_start[r] + rank[e] -------
__global__ void scatter_kernel(const int* __restrict__ rows,
                               const int* __restrict__ cols,
                               const float* __restrict__ vals) {
    int e = blockIdx.x * 256 + threadIdx.x;
    int r = rows[e];
    int pos = __ldg(&g_row_start[r]) + (int)g_rank[e];
    float v = vals[e];
    __half2 vh = __floats2half2_rn(v, v);
    g_edges[pos] = make_uint2((unsigned)cols[e], *(unsigned*)&vh);
}

// ---------------- SpMM: fp16 gather + HFMA2, fp32 accum, fp16 store ---------
__global__ void spmm_csr_kernel(int layer) {
    int w    = (blockIdx.x * blockDim.x + threadIdx.x) >> 5;
    int lane = threadIdx.x & 31;
    if (w >= N_NODES) return;
    const __half2* __restrict__ xh =
        (const __half2*)g_Xh + (size_t)layer * (NE / 2) + lane;
    int s = __ldg(&g_row_start[w]);
    int e = __ldg(&g_row_start[w + 1]);

    float ax = 0.f, ay = 0.f;
    int t = s;

    if ((t & 1) && t < e) {
        uint2 kv = g_edges[t];
        __half2 p = __hmul2(as_h2(kv.y), xh[(size_t)kv.x * 32]);
        float2 f = __half22float2(p);
        ax += f.x; ay += f.y;
        t++;
    }

    for (; t + 8 <= e; t += 8) {
        const uint4* ep = (const uint4*)(g_edges + t);
        uint4 e01 = ep[0];
        uint4 e23 = ep[1];
        uint4 e45 = ep[2];
        uint4 e67 = ep[3];
        __half2 x0 = xh[(size_t)e01.x * 32];
        __half2 x1 = xh[(size_t)e01.z * 32];
        __half2 x2 = xh[(size_t)e23.x * 32];
        __half2 x3 = xh[(size_t)e23.z * 32];
        __half2 x4 = xh[(size_t)e45.x * 32];
        __half2 x5 = xh[(size_t)e45.z * 32];
        __half2 x6 = xh[(size_t)e67.x * 32];
        __half2 x7 = xh[(size_t)e67.z * 32];
        __half2 a0 = __hmul2(as_h2(e01.y), x0);
        a0 = __hfma2(as_h2(e01.w), x1, a0);
        a0 = __hfma2(as_h2(e23.y), x2, a0);
        a0 = __hfma2(as_h2(e23.w), x3, a0);
        __half2 a1 = __hmul2(as_h2(e45.y), x4);
        a1 = __hfma2(as_h2(e45.w), x5, a1);
        a1 = __hfma2(as_h2(e67.y), x6, a1);
        a1 = __hfma2(as_h2(e67.w), x7, a1);
        float2 f0 = __half22float2(a0);
        float2 f1 = __half22float2(a1);
        ax += f0.x + f1.x;
        ay += f0.y + f1.y;
    }

    if (t < e) {
        uint2 kv = g_edges[t];
        __half2 at = __hmul2(as_h2(kv.y), xh[(size_t)kv.x * 32]);
        for (t++; t < e; t++) {
            kv = g_edges[t];
            at = __hfma2(as_h2(kv.y), xh[(size_t)kv.x * 32], at);
        }
        float2 ft = __half22float2(at);
        ax += ft.x; ay += ft.y;
    }

    __half2 hres = __floats2half2_rn(ax, ay);
    ((unsigned*)g_sideLh)[(size_t)w * 32 + lane] = *(unsigned*)&hres;
}

// ---------------- HMMA layer: [li|in](64x128) @ [W1;W2](128x64) -------------
__global__ void __launch_bounds__(256) layer_mma_kernel(
        const float* __restrict__ W1, const float* __restrict__ b1,
        const float* __restrict__ W2, const float* __restrict__ b2,
        int layer) {
    __shared__ __align__(16) __half Ash[64 * 128];   // 16KB
    __shared__ __align__(16) __half Bsh[128 * 64];   // 16KB
    __shared__ float bs[64];
    __shared__ float rowss[64][2];

    const __half* __restrict__ xk = g_Xh + (size_t)layer * NE;
    __half* __restrict__ xo       = g_Xh + (size_t)(layer + 1) * NE;

    int tid  = threadIdx.x;
    int base = blockIdx.x * 64;

    if (tid < 64) bs[tid] = b1[tid] + b2[tid];

    // ---- stage B = [W1;W2] fp16 ----
    {
        int k = tid >> 1, hf = tid & 1;
        const float* wrow = (k < 64) ? (W1 + k * 64 + hf * 32)
                                     : (W2 + (k - 64) * 64 + hf * 32);
        unsigned h[16];
#pragma unroll
        for (int i = 0; i < 8; i++) {
            float4 w = ((const float4*)wrow)[i];
            __half2 p0 = __floats2half2_rn(w.x, w.y);
            __half2 p1 = __floats2half2_rn(w.z, w.w);
            h[i * 2]     = *(unsigned*)&p0;
            h[i * 2 + 1] = *(unsigned*)&p1;
        }
        char* brow = (char*)Bsh + k * 128;
        int ksw = k & 7;
#pragma unroll
        for (int u = 0; u < 4; u++) {
            int unit = hf * 4 + u;
            *(uint4*)(brow + ((unit ^ ksw) << 4)) =
                make_uint4(h[u * 4], h[u * 4 + 1], h[u * 4 + 2], h[u * 4 + 3]);
        }
    }

    // ---- stage A = [li|in] fp16 from half2 inputs ----
    {
        int r = tid >> 2, qd = tid & 3;
        int rg = base + r;
        unsigned li_h[8], in_h[8];
        if (rg < N_NODES) {
            const uint4* sp = (const uint4*)(g_sideLh + (size_t)rg * EMB + qd * 16);
            const uint4* ap = (const uint4*)(xk       + (size_t)rg * EMB + qd * 16);
#pragma unroll
            for (int i = 0; i < 2; i++) {
                uint4 sv = sp[i], av = ap[i];
                const unsigned* su = (const unsigned*)&sv;
                const unsigned* au = (const unsigned*)&av;
#pragma unroll
                for (int p = 0; p < 4; p++) {
                    float2 s2 = __half22float2(as_h2(su[p]));
                    float2 a2 = __half22float2(as_h2(au[p]));
                    __half2 l = __floats2half2_rn(s2.x + a2.x, s2.y + a2.y);
                    __half2 n = __floats2half2_rn(s2.x * a2.x, s2.y * a2.y);
                    li_h[i * 4 + p] = *(unsigned*)&l;
                    in_h[i * 4 + p] = *(unsigned*)&n;
                }
            }
        } else {
#pragma unroll
            for (int i = 0; i < 8; i++) { li_h[i] = 0u; in_h[i] = 0u; }
        }
        char* arow = (char*)Ash + r * 256;
        int rsw = r & 7;
        *(uint4*)(arow + (((2 * qd)     ^ rsw) << 4)) =
            make_uint4(li_h[0], li_h[1], li_h[2], li_h[3]);
        *(uint4*)(arow + (((2 * qd + 1) ^ rsw) << 4)) =
            make_uint4(li_h[4], li_h[5], li_h[6], li_h[7]);
        *(uint4*)(arow + (((8 + 2 * qd)     ^ rsw) << 4)) =
            make_uint4(in_h[0], in_h[1], in_h[2], in_h[3]);
        *(uint4*)(arow + (((8 + 2 * qd + 1) ^ rsw) << 4)) =
            make_uint4(in_h[4], in_h[5], in_h[6], in_h[7]);
    }
    __syncthreads();

    // ---- MMA: warp = 4 m-tiles x 2 n-tiles(32); K=128 in 8 steps ----
    int lane = tid & 31, warp = tid >> 5;
    int mt = warp >> 1, nt2 = warp & 1;

    float acc[4][4];
#pragma unroll
    for (int j = 0; j < 4; j++)
#pragma unroll
        for (int q = 0; q < 4; q++) acc[j][q] = 0.f;

    unsigned a_base = smem_u32(Ash);
    unsigned b_base = smem_u32(Bsh);

    int ar = mt * 16 + (lane & 15);
    unsigned a_row_addr = a_base + ar * 256;
    int a_swz = ar & 7;
    int a_ub  = lane >> 4;

    int bk = lane & 15;
    int b_ub = lane >> 4;

#pragma unroll
    for (int s = 0; s < 8; s++) {
        unsigned a0, a1, a2, a3;
        int au = (2 * s + a_ub) ^ a_swz;
        ldsm_x4(a0, a1, a2, a3, a_row_addr + (au << 4));

        int kk = s * 16 + bk;
        unsigned b_row_addr = b_base + kk * 128;
        int ksw = kk & 7;
#pragma unroll
        for (int half = 0; half < 2; half++) {
            int u0 = nt2 * 4 + half * 2;
            unsigned r0, r1, r2, r3;
            int bu = (u0 + b_ub) ^ ksw;
            ldsm_x4t(r0, r1, r2, r3, b_row_addr + (bu << 4));
            mma16816(acc[half * 2 + 0], a0, a1, a2, a3, r0, r1);
            mma16816(acc[half * 2 + 1], a0, a1, a2, a3, r2, r3);
        }
    }

    // ---- epilogue: bias + leaky + row L2 normalize + fp16 store ----
    int g  = lane >> 2, tg = lane & 3;
    int r_lo = mt * 16 + g, r_hi = r_lo + 8;

    float s_lo = 0.f, s_hi = 0.f;
#pragma unroll
    for (int j = 0; j < 4; j++) {
        int c = nt2 * 32 + j * 8 + tg * 2;
        float bb0 = bs[c], bb1 = bs[c + 1];
        float v0 = acc[j][0] + bb0, v1 = acc[j][1] + bb1;
        float v2 = acc[j][2] + bb0, v3 = acc[j][3] + bb1;
        v0 = v0 > 0.f ? v0 : 0.01f * v0;
        v1 = v1 > 0.f ? v1 : 0.01f * v1;
        v2 = v2 > 0.f ? v2 : 0.01f * v2;
        v3 = v3 > 0.f ? v3 : 0.01f * v3;
        acc[j][0] = v0; acc[j][1] = v1; acc[j][2] = v2; acc[j][3] = v3;
        s_lo += v0 * v0 + v1 * v1;
        s_hi += v2 * v2 + v3 * v3;
    }
    s_lo += __shfl_xor_sync(0xffffffffu, s_lo, 1);
    s_lo += __shfl_xor_sync(0xffffffffu, s_lo, 2);
    s_hi += __shfl_xor_sync(0xffffffffu, s_hi, 1);
    s_hi += __shfl_xor_sync(0xffffffffu, s_hi, 2);
    if (tg == 0) {
        rowss[r_lo][nt2] = s_lo;
        rowss[r_hi][nt2] = s_hi;
    }
    __syncthreads();

    float inv_lo = 1.0f / fmaxf(sqrtf(rowss[r_lo][0] + rowss[r_lo][1]), 1e-12f);
    float inv_hi = 1.0f / fmaxf(sqrtf(rowss[r_hi][0] + rowss[r_hi][1]), 1e-12f);

    int rg_lo = base + r_lo, rg_hi = base + r_hi;

#pragma unroll
    for (int j = 0; j < 4; j++) {
        int c = nt2 * 32 + j * 8 + tg * 2;
        if (rg_lo < N_NODES) {
            __half2 h = __floats2half2_rn(acc[j][0] * inv_lo, acc[j][1] * inv_lo);
            *(unsigned*)(xo + (size_t)rg_lo * EMB + c) = *(unsigned*)&h;
        }
        if (rg_hi < N_NODES) {
            __half2 h = __floats2half2_rn(acc[j][2] * inv_hi, acc[j][3] * inv_hi);
            *(unsigned*)(xo + (size_t)rg_hi * EMB + c) = *(unsigned*)&h;
        }
    }
}

// ---------------- BPR loss (fp16 plane reads, fp32 math) --------------------
__global__ void loss_kernel(const int* __restrict__ u,
                            const int* __restrict__ ii,
                            const int* __restrict__ jj,
                            float* __restrict__ out) {
    int gw   = (blockIdx.x * blockDim.x + threadIdx.x) >> 5;
    int lane = threadIdx.x & 31;

    float contrib = 0.f;
    if (gw < BATCH) {
        int uu = u[gw];
        int pi = N_USERS + ii[gw];
        int nj = N_USERS + jj[gw];
        float dui = 0.f, duj = 0.f, l2 = 0.f;
#pragma unroll
        for (int c = 0; c < N_LAYERS + 1; c++) {
            const __half2* base = (const __half2*)g_Xh + (size_t)c * (NE / 2);
            float2 uv = __half22float2(base[(size_t)uu * 32 + lane]);
            float2 pv = __half22float2(base[(size_t)pi * 32 + lane]);
            float2 nv = __half22float2(base[(size_t)nj * 32 + lane]);
            dui += uv.x * pv.x + uv.y * pv.y;
            duj += uv.x * nv.x + uv.y * nv.y;
            l2  += uv.x * uv.x + uv.y * uv.y
                 + pv.x * pv.x + pv.y * pv.y
                 + nv.x * nv.x + nv.y * nv.y;
        }
#pragma unroll
        for (int o = 16; o; o >>= 1) {
            dui += __shfl_xor_sync(0xffffffffu, dui, o);
            duj += __shfl_xor_sync(0xffffffffu, duj, o);
            l2  += __shfl_xor_sync(0xffffffffu, l2,  o);
        }
        if (lane == 0) {
            float xv = dui - duj;
            float ls = fminf(xv, 0.f) - log1pf(expf(-fabsf(xv)));
            contrib = (-ls + REG_C * 0.5f * l2) * (1.0f / (float)BATCH);
        }
    }

    __shared__ float sred[8];
    if (lane == 0) sred[threadIdx.x >> 5] = contrib;
    __syncthreads();
    if (threadIdx.x == 0) {
        float s = 0.f;
#pragma unroll
        for (int q = 0; q < 8; q++) s += sred[q];
        atomicAdd(out, s);
    }
}

// ---------------------------------------------------------------------------
extern "C" void kernel_launch(void* const* d_in, const int* in_sizes, int n_in,
                              void* d_out, int out_size) {
    const int*   rows     = (const int*)  d_in[0];
    const int*   cols     = (const int*)  d_in[1];
    const float* vals     = (const float*)d_in[2];
    const float* user_emb = (const float*)d_in[3];
    const float* item_emb = (const float*)d_in[4];
    const float* W_one    = (const float*)d_in[5];
    const float* b_one    = (const float*)d_in[6];
    const float* W_two    = (const float*)d_in[7];
    const float* b_two    = (const float*)d_in[8];
    const int*   u        = (const int*)  d_in[9];
    const int*   i        = (const int*)  d_in[10];
    const int*   j        = (const int*)  d_in[11];
    float* out = (float*)d_out;
    (void)in_sizes; (void)n_in; (void)out_size;

    hist_ego_kernel<<<HIST_GRID + EGO_GRID, 256>>>(rows, user_emb, item_emb, out);
    scan123_kernel<<<NBLK, 256>>>();
    scatter_kernel<<<HIST_GRID, 256>>>(rows, cols, vals);

    for (int k = 0; k < N_LAYERS; k++) {
        spmm_csr_kernel<<<(N_NODES * 32) / 256, 256>>>(k);   // k=0 -> launch #4
        layer_mma_kernel<<<LGRID, 256>>>(
            W_one + k * EMB * EMB, b_one + k * EMB,
            W_two + k * EMB * EMB, b_two + k * EMB, k);
    }

    loss_kernel<<<BATCH / 8, 256>>>(u, i, j, out);
}

// round 16
// speedup vs baseline: 1.2651x; 1.2651x over previous
#include <cuda_runtime.h>
#include <cuda_fp16.h>
#include <math.h>

#define N_USERS 100000
#define N_NODES 150000
#define NNZ     4800000
#define EMB     64
#define N_LAYERS 3
#define BATCH   4096
#define REG_C   1e-5f
#define NE      (N_NODES * EMB)
#define HIST_SZ 150016
#define NBLK    586                      // scan blocks: 586*256 = 150016
#define HIST_GRID (NNZ / 256)            // 18750
#define EGO_GRID ((NE / 4) / 256)        // 9375
#define NLIST   (3 * BATCH)              // 12288 loss-gather nodes
#define LIST_GRID (NLIST / 256)          // 48
#define LGRID   ((N_NODES + 63) / 64)    // 2344
#define LGRID_S (NLIST / 64)             // 192

typedef unsigned long long u64;

// ---------------- scratch (alloc-free rule: __device__ globals) ------------
__device__ __half g_Xh[(N_LAYERS + 1) * NE]; // 76.8 MB fp16 planes 0..3
__device__ __half g_sideLh[NE];              // 19.2 MB fp16 spmm output
__device__ int    g_hist[HIST_SZ];           // zero at load; self-zeroed each pass
__device__ int    g_row_start[HIST_SZ];
__device__ int    g_cursor[HIST_SZ];
__device__ int    g_blocksum[NBLK];
__device__ int    g_list[NLIST];             // loss-gather node ids
__device__ uint2  g_edges[NNZ];              // (col, val as dup half2)
__device__ volatile unsigned g_bar_gen;
__device__ unsigned g_bar_ctr;

// ---------------- helpers ----------------------------------------------------
__device__ __forceinline__ __half2 as_h2(unsigned u) {
    __half2 h; *(unsigned*)&h = u; return h;
}
__device__ __forceinline__ unsigned smem_u32(const void* p) {
    return (unsigned)__cvta_generic_to_shared(p);
}
__device__ __forceinline__ void ldsm_x4(unsigned& r0, unsigned& r1,
                                        unsigned& r2, unsigned& r3,
                                        unsigned addr) {
    asm volatile("ldmatrix.sync.aligned.m8n8.x4.shared.b16 {%0,%1,%2,%3}, [%4];"
                 : "=r"(r0), "=r"(r1), "=r"(r2), "=r"(r3) : "r"(addr));
}
__device__ __forceinline__ void ldsm_x4t(unsigned& r0, unsigned& r1,
                                         unsigned& r2, unsigned& r3,
                                         unsigned addr) {
    asm volatile("ldmatrix.sync.aligned.m8n8.x4.trans.shared.b16 {%0,%1,%2,%3}, [%4];"
                 : "=r"(r0), "=r"(r1), "=r"(r2), "=r"(r3) : "r"(addr));
}
__device__ __forceinline__ void mma16816(float* c,
                                         unsigned a0, unsigned a1,
                                         unsigned a2, unsigned a3,
                                         unsigned b0, unsigned b1) {
    asm volatile(
        "mma.sync.aligned.m16n8k16.row.col.f32.f16.f16.f32 "
        "{%0,%1,%2,%3}, {%4,%5,%6,%7}, {%8,%9}, {%0,%1,%2,%3};"
        : "+f"(c[0]), "+f"(c[1]), "+f"(c[2]), "+f"(c[3])
        : "r"(a0), "r"(a1), "r"(a2), "r"(a3), "r"(b0), "r"(b1));
}

// ---------------- fused: out=0 + hist + ego copy + loss node list -----------
__global__ void hist_ego_kernel(const int* __restrict__ rows,
                                const float* __restrict__ ue,
                                const float* __restrict__ ie,
                                const int* __restrict__ u,
                                const int* __restrict__ ii,
                                const int* __restrict__ jj,
                                float* out) {
    int b = blockIdx.x;
    if (b == 0 && threadIdx.x == 0) *out = 0.f;
    if (b < HIST_GRID) {
        int e = b * 256 + threadIdx.x;
        atomicAdd(&g_hist[rows[e]], 1);
    } else if (b < HIST_GRID + EGO_GRID) {
        int idx = (b - HIST_GRID) * 256 + threadIdx.x;   // float4 index
        const int UF = (N_USERS * EMB) / 4;
        float4 v = (idx < UF) ? ((const float4*)ue)[idx]
                              : ((const float4*)ie)[idx - UF];
        __half2 h0 = __floats2half2_rn(v.x, v.y);
        __half2 h1 = __floats2half2_rn(v.z, v.w);
        ((uint2*)g_Xh)[idx] = make_uint2(*(unsigned*)&h0, *(unsigned*)&h1);
    } else {
        int idx = (b - HIST_GRID - EGO_GRID) * 256 + threadIdx.x;  // 0..12287
        int v;
        if (idx < BATCH)            v = u[idx];
        else if (idx < 2 * BATCH)   v = N_USERS + ii[idx - BATCH];
        else                        v = N_USERS + jj[idx - 2 * BATCH];
        g_list[idx] = v;
    }
}

// ---------------- single-kernel 3-stage scan (in-kernel grid barrier) -------
__global__ void __launch_bounds__(256) scan123_kernel() {
    __shared__ int s[256];
    __shared__ int red[256];
    int t = threadIdx.x;
    int b = blockIdx.x;
    int i = b * 256 + t;

    int v = g_hist[i];
    g_hist[i] = 0;
    s[t] = v; __syncthreads();
#pragma unroll
    for (int off = 1; off < 256; off <<= 1) {
        int add = (t >= off) ? s[t - off] : 0;
        __syncthreads();
        s[t] += add;
        __syncthreads();
    }
    if (t == 255) g_blocksum[b] = s[255];

    __threadfence();
    __syncthreads();
    if (t == 0) {
        unsigned gen = g_bar_gen;
        __threadfence();
        unsigned old = atomicAdd(&g_bar_ctr, 1u);
        if (old == NBLK - 1) {
            g_bar_ctr = 0;
            __threadfence();
            g_bar_gen = gen + 1;
        } else {
            while (g_bar_gen == gen) { }
        }
    }
    __syncthreads();
    __threadfence();

    int acc = 0;
    for (int k = t; k < b; k += 256) acc += g_blocksum[k];
    red[t] = acc; __syncthreads();
#pragma unroll
    for (int off = 128; off; off >>= 1) {
        if (t < off) red[t] += red[t + off];
        __syncthreads();
    }
    int val = (s[t] - v) + red[0];
    g_row_start[i] = val;
    g_cursor[i]    = val;
}

// ---------------- scatter edges into CSR order (R14 atomic cursor) ----------
__global__ void scatter_kernel(const int* __restrict__ rows,
                               const int* __restrict__ cols,
                               const float* __restrict__ vals) {
    int e = blockIdx.x * 256 + threadIdx.x;
    int r = rows[e];
    int pos = atomicAdd(&g_cursor[r], 1);
    float v = vals[e];
    __half2 vh = __floats2half2_rn(v, v);
    g_edges[pos] = make_uint2((unsigned)cols[e], *(unsigned*)&vh);
}

// ---------------- SpMM: fp16 gather + HFMA2 (R12 body); optional row list ---
__global__ void spmm_csr_kernel(int layer, int use_list) {
    int wi   = (blockIdx.x * blockDim.x + threadIdx.x) >> 5;
    int lane = threadIdx.x & 31;
    int w;
    if (use_list) {
        if (wi >= NLIST) return;
        w = g_list[wi];                  // dups recompute identical values
    } else {
        if (wi >= N_NODES) return;
        w = wi;
    }
    const __half2* __restrict__ xh =
        (const __half2*)g_Xh + (size_t)layer * (NE / 2) + lane;
    int s = __ldg(&g_row_start[w]);
    int e = __ldg(&g_row_start[w + 1]);

    float ax = 0.f, ay = 0.f;
    int t = s;

    if ((t & 1) && t < e) {
        uint2 kv = g_edges[t];
        __half2 p = __hmul2(as_h2(kv.y), xh[(size_t)kv.x * 32]);
        float2 f = __half22float2(p);
        ax += f.x; ay += f.y;
        t++;
    }

    for (; t + 8 <= e; t += 8) {
        const uint4* ep = (const uint4*)(g_edges + t);
        uint4 e01 = ep[0];
        uint4 e23 = ep[1];
        uint4 e45 = ep[2];
        uint4 e67 = ep[3];
        __half2 x0 = xh[(size_t)e01.x * 32];
        __half2 x1 = xh[(size_t)e01.z * 32];
        __half2 x2 = xh[(size_t)e23.x * 32];
        __half2 x3 = xh[(size_t)e23.z * 32];
        __half2 x4 = xh[(size_t)e45.x * 32];
        __half2 x5 = xh[(size_t)e45.z * 32];
        __half2 x6 = xh[(size_t)e67.x * 32];
        __half2 x7 = xh[(size_t)e67.z * 32];
        __half2 a0 = __hmul2(as_h2(e01.y), x0);
        a0 = __hfma2(as_h2(e01.w), x1, a0);
        a0 = __hfma2(as_h2(e23.y), x2, a0);
        a0 = __hfma2(as_h2(e23.w), x3, a0);
        __half2 a1 = __hmul2(as_h2(e45.y), x4);
        a1 = __hfma2(as_h2(e45.w), x5, a1);
        a1 = __hfma2(as_h2(e67.y), x6, a1);
        a1 = __hfma2(as_h2(e67.w), x7, a1);
        float2 f0 = __half22float2(a0);
        float2 f1 = __half22float2(a1);
        ax += f0.x + f1.x;
        ay += f0.y + f1.y;
    }

    if (t < e) {
        uint2 kv = g_edges[t];
        __half2 at = __hmul2(as_h2(kv.y), xh[(size_t)kv.x * 32]);
        for (t++; t < e; t++) {
            kv = g_edges[t];
            at = __hfma2(as_h2(kv.y), xh[(size_t)kv.x * 32], at);
        }
        float2 ft = __half22float2(at);
        ax += ft.x; ay += ft.y;
    }

    __half2 hres = __floats2half2_rn(ax, ay);
    ((unsigned*)g_sideLh)[(size_t)w * 32 + lane] = *(unsigned*)&hres;
}

// ---------------- HMMA layer (R13/14); optional row list for layer 3 --------
__global__ void __launch_bounds__(256) layer_mma_kernel(
        const float* __restrict__ W1, const float* __restrict__ b1,
        const float* __restrict__ W2, const float* __restrict__ b2,
        int layer, int use_list) {
    __shared__ __align__(16) __half Ash[64 * 128];   // 16KB
    __shared__ __align__(16) __half Bsh[128 * 64];   // 16KB
    __shared__ float bs[64];
    __shared__ float rowss[64][2];
    __shared__ int   rowid[64];

    const __half* __restrict__ xk = g_Xh + (size_t)layer * NE;
    __half* __restrict__ xo       = g_Xh + (size_t)(layer + 1) * NE;

    int tid  = threadIdx.x;
    int base = blockIdx.x * 64;

    if (tid < 64) {
        bs[tid] = b1[tid] + b2[tid];
        int rg = use_list ? g_list[base + tid]
                          : ((base + tid < N_NODES) ? base + tid : -1);
        rowid[tid] = rg;
    }

    // ---- stage B = [W1;W2] fp16 ----
    {
        int k = tid >> 1, hf = tid & 1;
        const float* wrow = (k < 64) ? (W1 + k * 64 + hf * 32)
                                     : (W2 + (k - 64) * 64 + hf * 32);
        unsigned h[16];
#pragma unroll
        for (int i = 0; i < 8; i++) {
            float4 w = ((const float4*)wrow)[i];
            __half2 p0 = __floats2half2_rn(w.x, w.y);
            __half2 p1 = __floats2half2_rn(w.z, w.w);
            h[i * 2]     = *(unsigned*)&p0;
            h[i * 2 + 1] = *(unsigned*)&p1;
        }
        char* brow = (char*)Bsh + k * 128;
        int ksw = k & 7;
#pragma unroll
        for (int u = 0; u < 4; u++) {
            int unit = hf * 4 + u;
            *(uint4*)(brow + ((unit ^ ksw) << 4)) =
                make_uint4(h[u * 4], h[u * 4 + 1], h[u * 4 + 2], h[u * 4 + 3]);
        }
    }
    __syncthreads();   // rowid ready before A staging

    // ---- stage A = [li|in] fp16 from half2 inputs ----
    {
        int r = tid >> 2, qd = tid & 3;
        int rg = rowid[r];
        unsigned li_h[8], in_h[8];
        if (rg >= 0) {
            const uint4* sp = (const uint4*)(g_sideLh + (size_t)rg * EMB + qd * 16);
            const uint4* ap = (const uint4*)(xk       + (size_t)rg * EMB + qd * 16);
#pragma unroll
            for (int i = 0; i < 2; i++) {
                uint4 sv = sp[i], av = ap[i];
                const unsigned* su = (const unsigned*)&sv;
                const unsigned* au = (const unsigned*)&av;
#pragma unroll
                for (int p = 0; p < 4; p++) {
                    float2 s2 = __half22float2(as_h2(su[p]));
                    float2 a2 = __half22float2(as_h2(au[p]));
                    __half2 l = __floats2half2_rn(s2.x + a2.x, s2.y + a2.y);
                    __half2 n = __floats2half2_rn(s2.x * a2.x, s2.y * a2.y);
                    li_h[i * 4 + p] = *(unsigned*)&l;
                    in_h[i * 4 + p] = *(unsigned*)&n;
                }
            }
        } else {
#pragma unroll
            for (int i = 0; i < 8; i++) { li_h[i] = 0u; in_h[i] = 0u; }
        }
        char* arow = (char*)Ash + r * 256;
        int rsw = r & 7;
        *(uint4*)(arow + (((2 * qd)     ^ rsw) << 4)) =
            make_uint4(li_h[0], li_h[1], li_h[2], li_h[3]);
        *(uint4*)(arow + (((2 * qd + 1) ^ rsw) << 4)) =
            make_uint4(li_h[4], li_h[5], li_h[6], li_h[7]);
        *(uint4*)(arow + (((8 + 2 * qd)     ^ rsw) << 4)) =
            make_uint4(in_h[0], in_h[1], in_h[2], in_h[3]);
        *(uint4*)(arow + (((8 + 2 * qd + 1) ^ rsw) << 4)) =
            make_uint4(in_h[4], in_h[5], in_h[6], in_h[7]);
    }
    __syncthreads();

    // ---- MMA: warp = 4 m-tiles x 2 n-tiles(32); K=128 in 8 steps ----
    int lane = tid & 31, warp = tid >> 5;
    int mt = warp >> 1, nt2 = warp & 1;

    float acc[4][4];
#pragma unroll
    for (int j = 0; j < 4; j++)
#pragma unroll
        for (int q = 0; q < 4; q++) acc[j][q] = 0.f;

    unsigned a_base = smem_u32(Ash);
    unsigned b_base = smem_u32(Bsh);

    int ar = mt * 16 + (lane & 15);
    unsigned a_row_addr = a_base + ar * 256;
    int a_swz = ar & 7;
    int a_ub  = lane >> 4;

    int bk = lane & 15;
    int b_ub = lane >> 4;

#pragma unroll
    for (int s = 0; s < 8; s++) {
        unsigned a0, a1, a2, a3;
        int au = (2 * s + a_ub) ^ a_swz;
        ldsm_x4(a0, a1, a2, a3, a_row_addr + (au << 4));

        int kk = s * 16 + bk;
        unsigned b_row_addr = b_base + kk * 128;
        int ksw = kk & 7;
#pragma unroll
        for (int half = 0; half < 2; half++) {
            int u0 = nt2 * 4 + half * 2;
            unsigned r0, r1, r2, r3;
            int bu = (u0 + b_ub) ^ ksw;
            ldsm_x4t(r0, r1, r2, r3, b_row_addr + (bu << 4));
            mma16816(acc[half * 2 + 0], a0, a1, a2, a3, r0, r1);
            mma16816(acc[half * 2 + 1], a0, a1, a2, a3, r2, r3);
        }
    }

    // ---- epilogue: bias + leaky + row L2 normalize + fp16 store ----
    int g  = lane >> 2, tg = lane & 3;
    int r_lo = mt * 16 + g, r_hi = r_lo + 8;

    float s_lo = 0.f, s_hi = 0.f;
#pragma unroll
    for (int j = 0; j < 4; j++) {
        int c = nt2 * 32 + j * 8 + tg * 2;
        float bb0 = bs[c], bb1 = bs[c + 1];
        float v0 = acc[j][0] + bb0, v1 = acc[j][1] + bb1;
        float v2 = acc[j][2] + bb0, v3 = acc[j][3] + bb1;
        v0 = v0 > 0.f ? v0 : 0.01f * v0;
        v1 = v1 > 0.f ? v1 : 0.01f * v1;
        v2 = v2 > 0.f ? v2 : 0.01f * v2;
        v3 = v3 > 0.f ? v3 : 0.01f * v3;
        acc[j][0] = v0; acc[j][1] = v1; acc[j][2] = v2; acc[j][3] = v3;
        s_lo += v0 * v0 + v1 * v1;
        s_hi += v2 * v2 + v3 * v3;
    }
    s_lo += __shfl_xor_sync(0xffffffffu, s_lo, 1);
    s_lo += __shfl_xor_sync(0xffffffffu, s_lo, 2);
    s_hi += __shfl_xor_sync(0xffffffffu, s_hi, 1);
    s_hi += __shfl_xor_sync(0xffffffffu, s_hi, 2);
    if (tg == 0) {
        rowss[r_lo][nt2] = s_lo;
        rowss[r_hi][nt2] = s_hi;
    }
    __syncthreads();

    float inv_lo = 1.0f / fmaxf(sqrtf(rowss[r_lo][0] + rowss[r_lo][1]), 1e-12f);
    float inv_hi = 1.0f / fmaxf(sqrtf(rowss[r_hi][0] + rowss[r_hi][1]), 1e-12f);

    int rg_lo = rowid[r_lo], rg_hi = rowid[r_hi];

#pragma unroll
    for (int j = 0; j < 4; j++) {
        int c = nt2 * 32 + j * 8 + tg * 2;
        if (rg_lo >= 0) {
            __half2 h = __floats2half2_rn(acc[j][0] * inv_lo, acc[j][1] * inv_lo);
            *(unsigned*)(xo + (size_t)rg_lo * EMB + c) = *(unsigned*)&h;
        }
        if (rg_hi >= 0) {
            __half2 h = __floats2half2_rn(acc[j][2] * inv_hi, acc[j][3] * inv_hi);
            *(unsigned*)(xo + (size_t)rg_hi * EMB + c) = *(unsigned*)&h;
        }
    }
}

// ---------------- BPR loss (fp16 plane reads, fp32 math) --------------------
__global__ void loss_kernel(const int* __restrict__ u,
                            const int* __restrict__ ii,
                            const int* __restrict__ jj,
                            float* __restrict__ out) {
    int gw   = (blockIdx.x * blockDim.x + threadIdx.x) >> 5;
    int lane = threadIdx.x & 31;

    float contrib = 0.f;
    if (gw < BATCH) {
        int uu = u[gw];
        int pi = N_USERS + ii[gw];
        int nj = N_USERS + jj[gw];
        float dui = 0.f, duj = 0.f, l2 = 0.f;
#pragma unroll
        for (int c = 0; c < N_LAYERS + 1; c++) {
            const __half2* base = (const __half2*)g_Xh + (size_t)c * (NE / 2);
            float2 uv = __half22float2(base[(size_t)uu * 32 + lane]);
            float2 pv = __half22float2(base[(size_t)pi * 32 + lane]);
            float2 nv = __half22float2(base[(size_t)nj * 32 + lane]);
            dui += uv.x * pv.x + uv.y * pv.y;
            duj += uv.x * nv.x + uv.y * nv.y;
            l2  += uv.x * uv.x + uv.y * uv.y
                 + pv.x * pv.x + pv.y * pv.y
                 + nv.x * nv.x + nv.y * nv.y;
        }
#pragma unroll
        for (int o = 16; o; o >>= 1) {
            dui += __shfl_xor_sync(0xffffffffu, dui, o);
            duj += __shfl_xor_sync(0xffffffffu, duj, o);
            l2  += __shfl_xor_sync(0xffffffffu, l2,  o);
        }
        if (lane == 0) {
            float xv = dui - duj;
            float ls = fminf(xv, 0.f) - log1pf(expf(-fabsf(xv)));
            contrib = (-ls + REG_C * 0.5f * l2) * (1.0f / (float)BATCH);
        }
    }

    __shared__ float sred[8];
    if (lane == 0) sred[threadIdx.x >> 5] = contrib;
    __syncthreads();
    if (threadIdx.x == 0) {
        float s = 0.f;
#pragma unroll
        for (int q = 0; q < 8; q++) s += sred[q];
        atomicAdd(out, s);
    }
}

// ---------------------------------------------------------------------------
extern "C" void kernel_launch(void* const* d_in, const int* in_sizes, int n_in,
                              void* d_out, int out_size) {
    const int*   rows     = (const int*)  d_in[0];
    const int*   cols     = (const int*)  d_in[1];
    const float* vals     = (const float*)d_in[2];
    const float* user_emb = (const float*)d_in[3];
    const float* item_emb = (const float*)d_in[4];
    const float* W_one    = (const float*)d_in[5];
    const float* b_one    = (const float*)d_in[6];
    const float* W_two    = (const float*)d_in[7];
    const float* b_two    = (const float*)d_in[8];
    const int*   u        = (const int*)  d_in[9];
    const int*   i        = (const int*)  d_in[10];
    const int*   j        = (const int*)  d_in[11];
    float* out = (float*)d_out;
    (void)in_sizes; (void)n_in; (void)out_size;

    hist_ego_kernel<<<HIST_GRID + EGO_GRID + LIST_GRID, 256>>>(
        rows, user_emb, item_emb, u, i, j, out);
    scan123_kernel<<<NBLK, 256>>>();
    scatter_kernel<<<HIST_GRID, 256>>>(rows, cols, vals);

    for (int k = 0; k < N_LAYERS; k++) {
        int sparse = (k == N_LAYERS - 1);
        if (sparse) {
            spmm_csr_kernel<<<(NLIST * 32) / 256, 256>>>(k, 1);
            layer_mma_kernel<<<LGRID_S, 256>>>(
                W_one + k * EMB * EMB, b_one + k * EMB,
                W_two + k * EMB * EMB, b_two + k * EMB, k, 1);
        } else {
            spmm_csr_kernel<<<(N_NODES * 32) / 256, 256>>>(k, 0);
            layer_mma_kernel<<<LGRID, 256>>>(
                W_one + k * EMB * EMB, b_one + k * EMB,
                W_two + k * EMB * EMB, b_two + k * EMB, k, 0);
        }
    }

    loss_kernel<<<BATCH / 8, 256>>>(u, i, j, out);
}